// round 5
// baseline (speedup 1.0000x reference)
#include <cuda_runtime.h>
#include <cuda_bf16.h>
#include <math.h>

#define B_   4
#define S_   1024
#define D_   512
#define V_   8192
#define NTOT (B_*S_)

// ------------------------- scratch (__device__ globals) -------------------------
__device__ float g_P [NTOT*D_];          // tanh(emb)
__device__ float g_C [NTOT*D_];          // cos(phases)
__device__ float g_Sn[NTOT*D_];          // sin(phases)
__device__ float g_feat[NTOT*2*D_];      // [cos(emb-cmean) | lc]  row stride 1024
__device__ float g_Wbig[2*D_*D_];        // [W_ctx@Wf2 ; Wf3]
__device__ float g_Ws5[5*D_];            // W_scale @ Wf0
__device__ float g_wsem[D_];             // W_sem @ Wf1
__device__ float g_biasc[D_];            // combined bias
__device__ float g_msc[NTOT*5];
__device__ float g_Dm[NTOT*9];           // raw band dots
__device__ float g_Dn[NTOT*9];           // normalized band dots
__device__ float g_sem[S_];
__device__ float g_cpart[B_*16*D_];
__device__ float g_cmean[B_*D_];
__device__ float g_y[NTOT*D_];
__device__ float g_x[NTOT*D_];
__device__ float g_t[NTOT*D_];
__device__ float g_h[NTOT*D_];

__device__ __forceinline__ float gelu_exact(float x){
    return 0.5f*x*(1.f + erff(x*0.70710678118654752440f));
}

__device__ __forceinline__ float blockReduceSum(float v){
    __shared__ float sh[8];
    int lane = threadIdx.x & 31, w = threadIdx.x >> 5;
    int nw = blockDim.x >> 5;
    __syncthreads();                 // protect sh reuse across calls
    #pragma unroll
    for (int o = 16; o; o >>= 1) v += __shfl_down_sync(0xffffffffu, v, o);
    if (lane == 0) sh[w] = v;
    __syncthreads();
    if (w == 0){
        v = (lane < nw) ? sh[lane] : 0.f;
        #pragma unroll
        for (int o = 16; o; o >>= 1) v += __shfl_down_sync(0xffffffffu, v, o);
        if (lane == 0) sh[0] = v;
    }
    __syncthreads();
    return sh[0];
}

// ------------------------- weight folding -------------------------
// Ws5 = W_scale@Wf0 ; wsem = W_sem@Wf1 ; biasc = b_fuse + b_scale@Wf0 + b_sem@Wf1 + b_ctx@Wf2
__global__ void foldw_kernel(const float* __restrict__ W_scale, const float* __restrict__ W_sem,
                             const float* __restrict__ b_scale, const float* __restrict__ b_sem,
                             const float* __restrict__ b_ctx,   const float* __restrict__ b_fuse,
                             const float* __restrict__ W_fuse)
{
    int c = threadIdx.x;          // 0..511
    int wb = blockIdx.x;          // 0..6
    if (wb < 5){
        float acc = 0.f;
        for (int d = 0; d < D_; d++)
            acc += W_scale[wb*D_ + d] * W_fuse[(size_t)d*D_ + c];
        g_Ws5[wb*D_ + c] = acc;
    } else if (wb == 5){
        float acc = 0.f;
        for (int d = 0; d < D_; d++)
            acc += W_sem[d] * W_fuse[(size_t)(D_ + d)*D_ + c];
        g_wsem[c] = acc;
    } else {
        float acc = b_fuse[c];
        for (int d = 0; d < D_; d++){
            acc += b_scale[d] * W_fuse[(size_t)d*D_ + c];
            acc += b_sem  [d] * W_fuse[(size_t)(D_ + d)*D_ + c];
            acc += b_ctx  [d] * W_fuse[(size_t)(2*D_ + d)*D_ + c];
        }
        g_biasc[c] = acc;
    }
}

// ------------------------- SGEMM: C[M,N] = A[M,K] @ B[K,N] (+bias) -------------------------
// 128x128 block tile, BK=16, 256 threads, 8x8 micro-tile.
__global__ void __launch_bounds__(256) sgemm_kernel(
    const float* __restrict__ A, const float* __restrict__ B,
    const float* __restrict__ bias, float* __restrict__ C,
    int M, int N, int K)
{
    __shared__ float As[16][136];    // transposed A tile, padded (136*4B = 16B-aligned rows)
    __shared__ float Bs[16][128];
    int tid = threadIdx.x;
    int bm = blockIdx.y*128, bn = blockIdx.x*128;
    int tx = tid & 15, ty = tid >> 4;
    int tm = ty*8, tn = tx*8;

    float acc[8][8];
    #pragma unroll
    for (int i = 0; i < 8; i++)
        #pragma unroll
        for (int j = 0; j < 8; j++) acc[i][j] = 0.f;

    int arow = tid >> 1;
    int acol = (tid & 1) * 8;
    const float* Aptr = A + (size_t)(bm + arow)*K + acol;
    int bk0 = tid >> 5;              // 0..7 (rows bk0 and bk0+8)
    int bnv = (tid & 31) * 4;
    const float* Bptr = B + (size_t)bk0*N + bn + bnv;

    for (int kt = 0; kt < K; kt += 16){
        float4 a0 = *(const float4*)(Aptr + kt);
        float4 a1 = *(const float4*)(Aptr + kt + 4);
        float4 b0 = *(const float4*)(Bptr + (size_t)kt*N);
        float4 b1 = *(const float4*)(Bptr + (size_t)(kt+8)*N);
        As[acol+0][arow] = a0.x; As[acol+1][arow] = a0.y;
        As[acol+2][arow] = a0.z; As[acol+3][arow] = a0.w;
        As[acol+4][arow] = a1.x; As[acol+5][arow] = a1.y;
        As[acol+6][arow] = a1.z; As[acol+7][arow] = a1.w;
        *(float4*)&Bs[bk0  ][bnv] = b0;
        *(float4*)&Bs[bk0+8][bnv] = b1;
        __syncthreads();
        #pragma unroll
        for (int k = 0; k < 16; k++){
            float4 av0 = *(float4*)&As[k][tm];
            float4 av1 = *(float4*)&As[k][tm+4];
            float4 bv0 = *(float4*)&Bs[k][tn];
            float4 bv1 = *(float4*)&Bs[k][tn+4];
            float a8[8] = {av0.x,av0.y,av0.z,av0.w,av1.x,av1.y,av1.z,av1.w};
            float b8[8] = {bv0.x,bv0.y,bv0.z,bv0.w,bv1.x,bv1.y,bv1.z,bv1.w};
            #pragma unroll
            for (int i = 0; i < 8; i++)
                #pragma unroll
                for (int j = 0; j < 8; j++)
                    acc[i][j] += a8[i]*b8[j];
        }
        __syncthreads();
    }

    float bv[8];
    #pragma unroll
    for (int j = 0; j < 8; j++) bv[j] = bias ? bias[bn+tn+j] : 0.f;
    #pragma unroll
    for (int i = 0; i < 8; i++){
        float4 o0, o1;
        o0.x = acc[i][0]+bv[0]; o0.y = acc[i][1]+bv[1];
        o0.z = acc[i][2]+bv[2]; o0.w = acc[i][3]+bv[3];
        o1.x = acc[i][4]+bv[4]; o1.y = acc[i][5]+bv[5];
        o1.z = acc[i][6]+bv[6]; o1.w = acc[i][7]+bv[7];
        float* cp = C + (size_t)(bm+tm+i)*N + bn + tn;
        *(float4*)cp     = o0;
        *(float4*)(cp+4) = o1;
    }
}

// ------------------------- phases + local coherence -------------------------
__global__ void phase_kernel(const float* __restrict__ emb){
    size_t i = (size_t)blockIdx.x*256 + threadIdx.x;   // over NTOT*D_
    float e = emb[i];
    float p = tanhf(e);
    float sp, cp; __sincosf(p, &sp, &cp);
    g_P[i] = p; g_C[i] = cp; g_Sn[i] = sp;
    size_t n = i >> 9; int d = (int)(i & 511);
    int t = (int)(n & (S_-1));
    float lc = (t < S_-1) ? cosf(emb[i + D_] - e) : 0.f;
    g_feat[n*(2*D_) + D_ + d] = lc;
}

// ------------------------- context mean -------------------------
__global__ void cmean_part_kernel(const float* __restrict__ emb, const float* __restrict__ mask){
    int ch = blockIdx.x, b = blockIdx.y;
    int t0 = ch*64;
    for (int d = threadIdx.x; d < D_; d += 256){
        float s = 0.f;
        for (int t = t0; t < t0+64; t++)
            s += emb[((size_t)(b*S_ + t))*D_ + d] * mask[b*S_ + t];
        g_cpart[(b*16+ch)*D_ + d] = s;
    }
}
__global__ void cmean_final_kernel(){
    int b = blockIdx.x, d = threadIdx.x;
    float s = 0.f;
    for (int c = 0; c < 16; c++) s += g_cpart[(b*16+c)*D_ + d];
    g_cmean[b*D_ + d] = s * (1.f/S_);
}
__global__ void ctxfeat_kernel(const float* __restrict__ emb){
    size_t i = (size_t)blockIdx.x*256 + threadIdx.x;   // over NTOT*D_
    size_t n = i >> 9; int d = (int)(i & 511);
    int b = (int)(n >> 10);
    g_feat[n*(2*D_) + d] = cosf(emb[i] - g_cmean[b*D_ + d]);
}

// ------------------------- banded token-similarity Gram -------------------------
// Dm[b,i,de] = dot(te[b,i], te[b,min(i+de,S-1)]),  de = 0..8.  (Dm[...,0] = ||te||^2)
__global__ void band_kernel(const float* __restrict__ tsm, const int* __restrict__ tok){
    __shared__ float Rs[24][136];
    __shared__ const float* rows[24];
    int b = blockIdx.y, i0 = blockIdx.x*16;
    int tid = threadIdx.x;                 // 192 threads
    if (tid < 24){
        int pos = min(i0 + tid, S_-1);
        rows[tid] = tsm + (size_t)tok[b*S_ + pos]*V_;
    }
    __syncthreads();
    int di = tid/9, de = tid%9;            // tid<144 valid pairs
    float acc = 0.f;
    for (int v0 = 0; v0 < V_; v0 += 128){
        #pragma unroll
        for (int l = tid; l < 24*32; l += 192){
            int r = l >> 5, cv = l & 31;
            *(float4*)&Rs[r][cv*4] = *(const float4*)(rows[r] + v0 + cv*4);
        }
        __syncthreads();
        if (tid < 144){
            int s2 = di + de;              // slot holds pos min(i0+s2, S-1) already
            #pragma unroll 8
            for (int c = 0; c < 32; c++){
                float4 a  = *(float4*)&Rs[di][c*4];
                float4 bb = *(float4*)&Rs[s2][c*4];
                acc += a.x*bb.x + a.y*bb.y + a.z*bb.z + a.w*bb.w;
            }
        }
        __syncthreads();
    }
    if (tid < 144)
        g_Dm[((size_t)(b*S_ + i0 + di))*9 + de] = acc;
}

__global__ void bandnorm_kernel(){
    int n = blockIdx.x*256 + threadIdx.x;  // over NTOT
    int b = n >> 10, i = n & (S_-1);
    float ni = fmaxf(sqrtf(g_Dm[(size_t)n*9]), 1e-12f);
    for (int de = 0; de < 9; de++){
        int j = min(i + de, S_-1);
        float nj = fmaxf(sqrtf(g_Dm[((size_t)(b*S_ + j))*9]), 1e-12f);
        g_Dn[(size_t)n*9 + de] = g_Dm[(size_t)n*9 + de] / (ni*nj);
    }
}

// ------------------------- semantic coherence -------------------------
__global__ void sem_kernel(){
    int i = blockIdx.x;                    // 0..S-1
    int tid = threadIdx.x;                 // 256
    float acc = 0.f;
    for (int b = 0; b < B_; b++){
        const float* Pi = g_P + ((size_t)(b*S_ + i))*D_;
        for (int k = 0; k < 17; k++){
            int j = i - 8 + k;
            if (j < 0 || j >= S_) continue;
            int lo = min(i, j), de = abs(i - j);
            float w = g_Dn[((size_t)(b*S_ + lo))*9 + de];
            const float* Pj = g_P + ((size_t)(b*S_ + j))*D_;
            float s = 0.f;
            for (int d = tid; d < D_; d += 256)
                s += __cosf((Pi[d] - Pj[d]) * w);
            acc += s;
        }
    }
    acc = blockReduceSum(acc);
    if (tid == 0){
        int lo = max(0, i-8), hi = min(S_-1, i+8);
        float counts = (float)(hi - lo + 1);
        g_sem[i] = acc / ((float)B_ * counts * (float)D_);
    }
}

// ------------------------- multi-scale coherence -------------------------
__global__ void mscale_kernel(){
    __shared__ float Ps[80][33], Cs[80][33], Ss[80][33];
    __shared__ float red[256*5];
    int b = blockIdx.y, t0 = blockIdx.x*64;
    int tid = threadIdx.x;                 // 256
    int tl = tid & 63, dg = tid >> 6;      // 64 t-slots x 4 d-groups
    float acc[5] = {0.f,0.f,0.f,0.f,0.f};
    for (int d0 = 0; d0 < D_; d0 += 32){
        for (int l = tid; l < 80*32; l += 256){
            int r = l >> 5, dc = l & 31;
            int gt = t0 + r;
            float p = 0.f, c = 0.f, s = 0.f;
            if (gt < S_){
                size_t idx = ((size_t)(b*S_ + gt))*D_ + d0 + dc;
                p = g_P[idx]; c = g_C[idx]; s = g_Sn[idx];
            }
            Ps[r][dc] = p; Cs[r][dc] = c; Ss[r][dc] = s;
        }
        __syncthreads();
        for (int dd = 0; dd < 8; dd++){
            int dc = dg*8 + dd;
            float sp = 0.f, sc = 0.f, ss = 0.f;
            #pragma unroll
            for (int r = 0; r < 16; r++){
                sp += Ps[tl+r][dc]; sc += Cs[tl+r][dc]; ss += Ss[tl+r][dc];
                if (r==0 || r==1 || r==3 || r==7 || r==15){
                    int sidx = (r==0)?0:(r==1)?1:(r==3)?2:(r==7)?3:4;
                    float inv = 1.f/(float)(r+1);
                    float wm = sp*inv;
                    float sv, cv; __sincosf(wm, &sv, &cv);
                    acc[sidx] += cv*(sc*inv) + sv*(ss*inv);
                }
            }
        }
        __syncthreads();
    }
    #pragma unroll
    for (int s = 0; s < 5; s++) red[tid*5 + s] = acc[s];
    __syncthreads();
    if (dg == 0){
        int t = t0 + tl;
        #pragma unroll
        for (int s5 = 0; s5 < 5; s5++){
            float v = red[tl*5+s5] + red[(tl+64)*5+s5]
                    + red[(tl+128)*5+s5] + red[(tl+192)*5+s5];
            int sv = 1 << s5;
            g_msc[((size_t)(b*S_ + t))*5 + s5] = (t + sv <= S_) ? v*(1.f/D_) : 0.f;
        }
    }
}

// ------------------------- fuse epilogue + LN1 + GELU -------------------------
__global__ void fuse_ln1_kernel(const float* __restrict__ g1, const float* __restrict__ b1){
    int n = blockIdx.x;                    // 0..NTOT-1
    int tid = threadIdx.x;                 // 128
    int t = n & (S_-1);
    float sem = g_sem[t];
    float m0 = g_msc[(size_t)n*5+0], m1 = g_msc[(size_t)n*5+1], m2 = g_msc[(size_t)n*5+2];
    float m3 = g_msc[(size_t)n*5+3], m4 = g_msc[(size_t)n*5+4];
    float v[4]; float s = 0.f;
    #pragma unroll
    for (int j = 0; j < 4; j++){
        int c = tid + 128*j;
        float x = g_y[(size_t)n*D_ + c] + g_biasc[c] + sem*g_wsem[c]
                + m0*g_Ws5[c] + m1*g_Ws5[D_+c] + m2*g_Ws5[2*D_+c]
                + m3*g_Ws5[3*D_+c] + m4*g_Ws5[4*D_+c];
        v[j] = x; s += x;
    }
    float mean = blockReduceSum(s) * (1.f/D_);
    float q = 0.f;
    #pragma unroll
    for (int j = 0; j < 4; j++){ float d = v[j]-mean; q += d*d; }
    float var = blockReduceSum(q) * (1.f/D_);
    float rstd = rsqrtf(var + 1e-5f);
    #pragma unroll
    for (int j = 0; j < 4; j++){
        int c = tid + 128*j;
        float h = (v[j]-mean)*rstd*g1[c] + b1[c];
        g_x[(size_t)n*D_ + c] = gelu_exact(h);
    }
}

// ------------------------- plain LayerNorm -------------------------
__global__ void ln_plain_kernel(const float* __restrict__ src, const float* __restrict__ g,
                                const float* __restrict__ b, float* __restrict__ dst){
    int n = blockIdx.x; int tid = threadIdx.x;      // 128
    const float* r = src + (size_t)n*D_;
    float v[4]; float s = 0.f;
    #pragma unroll
    for (int j = 0; j < 4; j++){ v[j] = r[tid + 128*j]; s += v[j]; }
    float mean = blockReduceSum(s) * (1.f/D_);
    float q = 0.f;
    #pragma unroll
    for (int j = 0; j < 4; j++){ float d = v[j]-mean; q += d*d; }
    float var = blockReduceSum(q) * (1.f/D_);
    float rstd = rsqrtf(var + 1e-5f);
    #pragma unroll
    for (int j = 0; j < 4; j++){
        int c = tid + 128*j;
        dst[(size_t)n*D_ + c] = (v[j]-mean)*rstd*g[c] + b[c];
    }
}

// ------------------------- residual add -------------------------
__global__ void resid_kernel(){
    size_t i = (size_t)blockIdx.x*256 + threadIdx.x;
    g_x[i] += gelu_exact(g_h[i]) * 0.1f;
}

// ------------------------- launch -------------------------
extern "C" void kernel_launch(void* const* d_in, const int* in_sizes, int n_in,
                              void* d_out, int out_size){
    (void)in_sizes; (void)n_in; (void)out_size;
    const float* emb     = (const float*)d_in[0];
    const int*   tok     = (const int*)  d_in[1];
    const float* mask    = (const float*)d_in[2];
    const float* tsm     = (const float*)d_in[3];
    const float* W_scale = (const float*)d_in[4];
    const float* b_scale = (const float*)d_in[5];
    const float* W_sem   = (const float*)d_in[6];
    const float* b_sem   = (const float*)d_in[7];
    const float* W_ctx   = (const float*)d_in[8];
    const float* b_ctx   = (const float*)d_in[9];
    const float* W_fuse  = (const float*)d_in[10];
    const float* b_fuse  = (const float*)d_in[11];
    const float* ln1g = (const float*)d_in[12]; const float* ln1b = (const float*)d_in[13];
    const float* ln2g = (const float*)d_in[14]; const float* ln2b = (const float*)d_in[15];
    const float* ln3g = (const float*)d_in[16]; const float* ln3b = (const float*)d_in[17];
    const float* We[3] = {(const float*)d_in[18], (const float*)d_in[20], (const float*)d_in[22]};
    const float* be[3] = {(const float*)d_in[19], (const float*)d_in[21], (const float*)d_in[23]};
    float* out = (float*)d_out;

    float *pWbig, *pFeat, *pY, *pX, *pT, *pH;
    cudaGetSymbolAddress((void**)&pWbig, g_Wbig);
    cudaGetSymbolAddress((void**)&pFeat, g_feat);
    cudaGetSymbolAddress((void**)&pY,    g_y);
    cudaGetSymbolAddress((void**)&pX,    g_x);
    cudaGetSymbolAddress((void**)&pT,    g_t);
    cudaGetSymbolAddress((void**)&pH,    g_h);

    // weight folding
    foldw_kernel<<<7, 512>>>(W_scale, W_sem, b_scale, b_sem, b_ctx, b_fuse, W_fuse);
    sgemm_kernel<<<dim3(4,4), 256>>>(W_ctx, W_fuse + (size_t)2*D_*D_, nullptr, pWbig,
                                     D_, D_, D_);
    cudaMemcpyAsync(pWbig + D_*D_, W_fuse + (size_t)3*D_*D_,
                    (size_t)D_*D_*sizeof(float), cudaMemcpyDeviceToDevice);

    // features
    phase_kernel  <<<NTOT*D_/256, 256>>>(emb);
    cmean_part_kernel <<<dim3(16, B_), 256>>>(emb, mask);
    cmean_final_kernel<<<B_, 512>>>();
    ctxfeat_kernel<<<NTOT*D_/256, 256>>>(emb);

    // banded similarity + sem
    band_kernel    <<<dim3(S_/16, B_), 192>>>(tsm, tok);
    bandnorm_kernel<<<NTOT/256, 256>>>();
    sem_kernel     <<<S_, 256>>>();

    // multi-scale coherence
    mscale_kernel<<<dim3(S_/64, B_), 256>>>();

    // fused projection
    sgemm_kernel<<<dim3(4,32), 256>>>(pFeat, pWbig, nullptr, pY, NTOT, D_, 2*D_);
    fuse_ln1_kernel<<<NTOT, 128>>>(ln1g, ln1b);

    // residual blocks
    for (int l = 0; l < 3; l++){
        ln_plain_kernel<<<NTOT, 128>>>(pX, ln2g, ln2b, pT);
        sgemm_kernel<<<dim3(4,32), 256>>>(pT, We[l], be[l], pH, NTOT, D_, D_);
        resid_kernel<<<NTOT*D_/256, 256>>>();
    }

    // final LN -> output
    ln_plain_kernel<<<NTOT, 128>>>(pX, ln3g, ln3b, out);
}